// round 14
// baseline (speedup 1.0000x reference)
#include <cuda_runtime.h>
#include <cuda_fp16.h>
#include <cstdint>

// Problem constants
#define BATCH 4
#define SEQ   2048
#define EMB   1024
#define HDIM  1024
#define NTHREADS 256

// GEMM tiling (R8-validated): CTA 128(M) x 256(N), warp tile 64x64, KC=64, 4 stages
#define KC      64
#define NSTG    4
#define ATILEB  (128 * 128)           // 16384 B
#define BTILEB  (256 * 128)           // 32768 B
#define VTILEB  (64 * 512)            // 32768 B : 64 k-rows x 512 B (256 e-cols)

// Scratch (static device allocations)
__device__ __half g_xh[(size_t)BATCH * SEQ * HDIM];      // fp16 x
__device__ __half g_wh[3][(size_t)EMB * HDIM];           // fp16 weights
__device__ __half g_qkvh[3][(size_t)BATCH * SEQ * EMB];  // fp16 Q,K,V
__device__ float  g_p[(size_t)BATCH * SEQ * SEQ];        // fp32 scores
__device__ __half g_ph[(size_t)BATCH * SEQ * SEQ];       // fp16 probs
__device__ float  g_po[(size_t)BATCH * 8 * 128 * EMB];   // pv split-K partials (mt>=8)

// ---------------------------------------------------------------------------
// PTX helpers
// ---------------------------------------------------------------------------
__device__ __forceinline__ void cp16(uint32_t dst, const void* src) {
    asm volatile("cp.async.ca.shared.global [%0], [%1], 16;" :: "r"(dst), "l"(src));
}
__device__ __forceinline__ void cp_commit() { asm volatile("cp.async.commit_group;"); }
template <int N>
__device__ __forceinline__ void cp_wait() { asm volatile("cp.async.wait_group %0;" :: "n"(N)); }

__device__ __forceinline__ void ldsm4(uint32_t* r, uint32_t addr) {
    asm volatile("ldmatrix.sync.aligned.m8n8.x4.shared.b16 {%0,%1,%2,%3}, [%4];"
                 : "=r"(r[0]), "=r"(r[1]), "=r"(r[2]), "=r"(r[3]) : "r"(addr));
}
__device__ __forceinline__ void ldsm4t(uint32_t* r, uint32_t addr) {
    asm volatile("ldmatrix.sync.aligned.m8n8.x4.trans.shared.b16 {%0,%1,%2,%3}, [%4];"
                 : "=r"(r[0]), "=r"(r[1]), "=r"(r[2]), "=r"(r[3]) : "r"(addr));
}
__device__ __forceinline__ void mma16(float* c, const uint32_t* a, const uint32_t* b) {
    asm volatile(
        "mma.sync.aligned.m16n8k16.row.col.f32.f16.f16.f32 "
        "{%0,%1,%2,%3}, {%4,%5,%6,%7}, {%8,%9}, {%0,%1,%2,%3};"
        : "+f"(c[0]), "+f"(c[1]), "+f"(c[2]), "+f"(c[3])
        : "r"(a[0]), "r"(a[1]), "r"(a[2]), "r"(a[3]), "r"(b[0]), "r"(b[1]));
}

// ---------------------------------------------------------------------------
// Kernel 0: single fp32 -> fp16 conversion pass for x + 3 weights.
// ---------------------------------------------------------------------------
#define XN4 ((BATCH * SEQ * HDIM) / 4)
#define WN4 ((EMB * HDIM) / 4)

__global__ void __launch_bounds__(NTHREADS)
cvt_kernel(const float4* __restrict__ xs, const float4* __restrict__ wq,
           const float4* __restrict__ wk, const float4* __restrict__ wv)
{
    int i = blockIdx.x * NTHREADS + threadIdx.x;
    const float4* src;
    __half* dst;
    int off;
    if (i < XN4)                { src = xs; dst = g_xh;    off = i; }
    else if (i < XN4 + WN4)     { src = wq; dst = g_wh[0]; off = i - XN4; }
    else if (i < XN4 + 2 * WN4) { src = wk; dst = g_wh[1]; off = i - XN4 - WN4; }
    else if (i < XN4 + 3 * WN4) { src = wv; dst = g_wh[2]; off = i - XN4 - 2 * WN4; }
    else return;
    float4 v = src[off];
    __half2 h0 = __floats2half2_rn(v.x, v.y);
    __half2 h1 = __floats2half2_rn(v.z, v.w);
    uint2 u;
    u.x = *reinterpret_cast<uint32_t*>(&h0);
    u.y = *reinterpret_cast<uint32_t*>(&h1);
    ((uint2*)dst)[off] = u;
}

// ---------------------------------------------------------------------------
// Kernel 1: QKV projection, NT fp16 GEMM + bias. grid (4, 64, 3). (R8 verbatim)
// ---------------------------------------------------------------------------
__global__ void __launch_bounds__(NTHREADS, 1)
qkv_kernel(const float* __restrict__ bi0,
           const float* __restrict__ bi1,
           const float* __restrict__ bi2)
{
    extern __shared__ char dsm[];
    const uint32_t Abase = (uint32_t)__cvta_generic_to_shared(dsm);
    const uint32_t Bbase = Abase + NSTG * ATILEB;

    const int which = blockIdx.z;
    const __half* Ag = g_xh;
    const __half* Bg = g_wh[which];
    const float* bias = (which == 0) ? bi0 : (which == 1) ? bi1 : bi2;
    __half* out = g_qkvh[which];

    const int m0 = blockIdx.y * 128, n0 = blockIdx.x * 256;
    const int tid = threadIdx.x;
    const int warp = tid >> 5, lane = tid & 31;
    const int wm = warp & 1, wn = warp >> 1;
    const int g = lane >> 2, tig = lane & 3;

    const int lr = tid >> 1;
    const int lc = (tid & 1) * 4;
    const __half* agp = Ag + (size_t)(m0 + lr) * HDIM;
    const __half* bgp0 = Bg + (size_t)(n0 + lr) * HDIM;
    const __half* bgp1 = Bg + (size_t)(n0 + lr + 128) * HDIM;
    const uint32_t lxor = (uint32_t)(lr & 7);

    const uint32_t a_row = (uint32_t)(wm * 64 + (lane & 15));
    const uint32_t a_chi = (uint32_t)(lane >> 4);
    const uint32_t a_xor = (uint32_t)(lane & 7);
    const uint32_t b_row = (uint32_t)(wn * 64 + (lane & 7) + ((lane >> 4) & 1) * 8);
    const uint32_t b_chi = (uint32_t)((lane >> 3) & 1);

    float acc[4][8][4];
#pragma unroll
    for (int i = 0; i < 4; i++)
#pragma unroll
        for (int j = 0; j < 8; j++)
#pragma unroll
            for (int k = 0; k < 4; k++) acc[i][j][k] = 0.f;

    auto pre = [&](int c, int s) {
        const __half* ap = agp + c * KC;
        const __half* bp0 = bgp0 + c * KC;
        const __half* bp1 = bgp1 + c * KC;
        const uint32_t as = Abase + s * ATILEB + lr * 128;
        const uint32_t bs0 = Bbase + s * BTILEB + lr * 128;
        const uint32_t bs1 = bs0 + 128 * 128;
#pragma unroll
        for (int j = 0; j < 4; j++) {
            const uint32_t c16 = lc + j;
            const uint32_t sw = (c16 ^ lxor) * 16;
            cp16(as + sw,  ap + c16 * 8);
            cp16(bs0 + sw, bp0 + c16 * 8);
            cp16(bs1 + sw, bp1 + c16 * 8);
        }
        cp_commit();
    };

    const int T = HDIM / KC;   // 16
    pre(0, 0); pre(1, 1); pre(2, 2);

    for (int t = 0; t < T; ++t) {
        if (t + 2 < T) cp_wait<2>(); else if (t + 1 < T) cp_wait<1>(); else cp_wait<0>();
        __syncthreads();
        if (t + 3 < T) pre(t + 3, (t + 3) & 3);

        const int s = t & 3;
        const uint32_t Ab = Abase + s * ATILEB;
        const uint32_t Bb = Bbase + s * BTILEB;
#pragma unroll
        for (int kk = 0; kk < 4; ++kk) {
            const uint32_t asw = ((kk * 2 + a_chi) ^ a_xor) * 16;
            const uint32_t bsw = ((kk * 2 + b_chi) ^ a_xor) * 16;
            uint32_t a[4][4];
#pragma unroll
            for (int mi = 0; mi < 4; ++mi)
                ldsm4(a[mi], Ab + (a_row + mi * 16) * 128 + asw);
            uint32_t b[4][4];
#pragma unroll
            for (int p = 0; p < 4; ++p)
                ldsm4(b[p], Bb + (b_row + p * 16) * 128 + bsw);
#pragma unroll
            for (int mi = 0; mi < 4; ++mi)
#pragma unroll
                for (int ni = 0; ni < 8; ++ni)
                    mma16(acc[mi][ni], a[mi], &b[ni >> 1][(ni & 1) * 2]);
        }
    }

#pragma unroll
    for (int mi = 0; mi < 4; ++mi) {
        const int row = m0 + wm * 64 + mi * 16 + g;
#pragma unroll
        for (int ni = 0; ni < 8; ++ni) {
            const int col = n0 + wn * 64 + ni * 8 + 2 * tig;
            const float b0v = bias[col], b1v = bias[col + 1];
            __half2 h0 = __floats2half2_rn(acc[mi][ni][0] + b0v, acc[mi][ni][1] + b1v);
            __half2 h1 = __floats2half2_rn(acc[mi][ni][2] + b0v, acc[mi][ni][3] + b1v);
            *(__half2*)(out + (size_t)row * EMB + col)       = h0;
            *(__half2*)(out + (size_t)(row + 8) * EMB + col) = h1;
        }
    }
}

// ---------------------------------------------------------------------------
// Kernel 2: scores, NT fp16 GEMM, causal tiles only (2*nt <= qt), fp32 out.
// grid (8, 16, 4). CTA tile 128 x 256. Diagonal tiles (2*nt == qt): right
// 128 cols fully masked & never read -> warps wn>=2 skip MMA/stores and the
// bs1 load stream is skipped. (Validated numerically in R12.)
// ---------------------------------------------------------------------------
__global__ void __launch_bounds__(NTHREADS, 1)
scores_kernel()
{
    const int qt = blockIdx.y, nt = blockIdx.x;
    if (2 * nt > qt) return;
    const int b = blockIdx.z;
    const bool diag = (2 * nt == qt);

    extern __shared__ char dsm[];
    const uint32_t Abase = (uint32_t)__cvta_generic_to_shared(dsm);
    const uint32_t Bbase = Abase + NSTG * ATILEB;

    const __half* Q  = g_qkvh[0] + (size_t)b * SEQ * EMB;
    const __half* Km = g_qkvh[1] + (size_t)b * SEQ * EMB;
    float* P = g_p + (size_t)b * SEQ * SEQ;

    const int m0 = qt * 128, n0 = nt * 256;
    const int tid = threadIdx.x;
    const int warp = tid >> 5, lane = tid & 31;
    const int wm = warp & 1, wn = warp >> 1;
    const int g = lane >> 2, tig = lane & 3;
    const bool active = !(diag && wn >= 2);

    const int lr = tid >> 1;
    const int lc = (tid & 1) * 4;
    const __half* agp = Q  + (size_t)(m0 + lr) * EMB;
    const __half* bgp0 = Km + (size_t)(n0 + lr) * EMB;
    const __half* bgp1 = Km + (size_t)(n0 + lr + 128) * EMB;
    const uint32_t lxor = (uint32_t)(lr & 7);

    const uint32_t a_row = (uint32_t)(wm * 64 + (lane & 15));
    const uint32_t a_chi = (uint32_t)(lane >> 4);
    const uint32_t a_xor = (uint32_t)(lane & 7);
    const uint32_t b_row = (uint32_t)(wn * 64 + (lane & 7) + ((lane >> 4) & 1) * 8);
    const uint32_t b_chi = (uint32_t)((lane >> 3) & 1);

    float acc[4][8][4];
#pragma unroll
    for (int i = 0; i < 4; i++)
#pragma unroll
        for (int j = 0; j < 8; j++)
#pragma unroll
            for (int k = 0; k < 4; k++) acc[i][j][k] = 0.f;

    auto pre = [&](int c, int s) {
        const __half* ap = agp + c * KC;
        const __half* bp0 = bgp0 + c * KC;
        const __half* bp1 = bgp1 + c * KC;
        const uint32_t as = Abase + s * ATILEB + lr * 128;
        const uint32_t bs0 = Bbase + s * BTILEB + lr * 128;
        const uint32_t bs1 = bs0 + 128 * 128;
#pragma unroll
        for (int j = 0; j < 4; j++) {
            const uint32_t c16 = lc + j;
            const uint32_t sw = (c16 ^ lxor) * 16;
            cp16(as + sw,  ap + c16 * 8);
            cp16(bs0 + sw, bp0 + c16 * 8);
            if (!diag) cp16(bs1 + sw, bp1 + c16 * 8);
        }
        cp_commit();
    };

    const int T = EMB / KC;   // 16
    pre(0, 0); pre(1, 1); pre(2, 2);

    for (int t = 0; t < T; ++t) {
        if (t + 2 < T) cp_wait<2>(); else if (t + 1 < T) cp_wait<1>(); else cp_wait<0>();
        __syncthreads();
        if (t + 3 < T) pre(t + 3, (t + 3) & 3);

        if (active) {
            const int s = t & 3;
            const uint32_t Ab = Abase + s * ATILEB;
            const uint32_t Bb = Bbase + s * BTILEB;
#pragma unroll
            for (int kk = 0; kk < 4; ++kk) {
                const uint32_t asw = ((kk * 2 + a_chi) ^ a_xor) * 16;
                const uint32_t bsw = ((kk * 2 + b_chi) ^ a_xor) * 16;
                uint32_t a[4][4];
#pragma unroll
                for (int mi = 0; mi < 4; ++mi)
                    ldsm4(a[mi], Ab + (a_row + mi * 16) * 128 + asw);
                uint32_t b[4][4];
#pragma unroll
                for (int p = 0; p < 4; ++p)
                    ldsm4(b[p], Bb + (b_row + p * 16) * 128 + bsw);
#pragma unroll
                for (int mi = 0; mi < 4; ++mi)
#pragma unroll
                    for (int ni = 0; ni < 8; ++ni)
                        mma16(acc[mi][ni], a[mi], &b[ni >> 1][(ni & 1) * 2]);
            }
        }
    }

    const float scale = 0.03125f;  // 1/sqrt(1024)
    if (active) {
#pragma unroll
        for (int mi = 0; mi < 4; ++mi) {
            const int row = m0 + wm * 64 + mi * 16 + g;
#pragma unroll
            for (int ni = 0; ni < 8; ++ni) {
                const int col = n0 + wn * 64 + ni * 8 + 2 * tig;
                float2 r0 = {acc[mi][ni][0] * scale, acc[mi][ni][1] * scale};
                float2 r1 = {acc[mi][ni][2] * scale, acc[mi][ni][3] * scale};
                *(float2*)(P + (size_t)row * SEQ + col)       = r0;
                *(float2*)(P + (size_t)(row + 8) * SEQ + col) = r1;
            }
        }
    }
}

// ---------------------------------------------------------------------------
// Kernel 3: row softmax over [0..q]; fp16 probs out; vectorized passes.
// ---------------------------------------------------------------------------
__global__ void __launch_bounds__(NTHREADS)
softmax_kernel()
{
    __shared__ float buf[SEQ];
    __shared__ float red[8];

    const int q = blockIdx.x & (SEQ - 1);
    const int b = blockIdx.x >> 11;
    const float* row = g_p + ((size_t)b * SEQ + q) * SEQ;
    __half* orow = g_ph + ((size_t)b * SEQ + q) * SEQ;
    const int n = q + 1;
    const int zend = ((q >> 7) + 1) << 7;
    const int tid = threadIdx.x;
    const int lane = tid & 31;
    const int wid = tid >> 5;

    const float4* row4 = (const float4*)row;
    float4* buf4 = (float4*)buf;
    const int n4 = n >> 2;

    float lmax = -1e30f;
    for (int i = tid; i < n4; i += NTHREADS) {
        float4 v = row4[i];
        buf4[i] = v;
        lmax = fmaxf(lmax, fmaxf(fmaxf(v.x, v.y), fmaxf(v.z, v.w)));
    }
    for (int i = (n4 << 2) + tid; i < n; i += NTHREADS) {
        float v = row[i];
        buf[i] = v;
        lmax = fmaxf(lmax, v);
    }
#pragma unroll
    for (int off = 16; off; off >>= 1)
        lmax = fmaxf(lmax, __shfl_xor_sync(0xffffffffu, lmax, off));
    if (lane == 0) red[wid] = lmax;
    __syncthreads();
    float gmax = red[0];
#pragma unroll
    for (int w = 1; w < 8; w++) gmax = fmaxf(gmax, red[w]);
    __syncthreads();

    float lsum = 0.f;
    for (int i = tid; i < n4; i += NTHREADS) {
        float4 v = buf4[i];
        v.x = __expf(v.x - gmax); v.y = __expf(v.y - gmax);
        v.z = __expf(v.z - gmax); v.w = __expf(v.w - gmax);
        buf4[i] = v;
        lsum += (v.x + v.y) + (v.z + v.w);
    }
    for (int i = (n4 << 2) + tid; i < n; i += NTHREADS) {
        float e = __expf(buf[i] - gmax);
        buf[i] = e;
        lsum += e;
    }
#pragma unroll
    for (int off = 16; off; off >>= 1)
        lsum += __shfl_xor_sync(0xffffffffu, lsum, off);
    if (lane == 0) red[wid] = lsum;
    __syncthreads();
    float gsum = red[0];
#pragma unroll
    for (int w = 1; w < 8; w++) gsum += red[w];

    const float inv = 1.f / gsum;
    const int n2 = n >> 1;
    __half2* orow2 = (__half2*)orow;
    const float2* buf2 = (const float2*)buf;
    for (int i = tid; i < n2; i += NTHREADS) {
        float2 v = buf2[i];
        orow2[i] = __floats2half2_rn(v.x * inv, v.y * inv);
    }
    for (int i = (n2 << 1) + tid; i < n; i += NTHREADS)
        orow[i] = __float2half_rn(buf[i] * inv);
    const __half hz = __float2half_rn(0.f);
    for (int i = n + tid; i < zend; i += NTHREADS) orow[i] = hz;
}

// ---------------------------------------------------------------------------
// Kernel 4: O = P @ V, NN fp16 GEMM (V via ldmatrix.trans).
// Split-K(2) for mt >= 8: grid (4, 24, 4), heavy chains first. (R11 verbatim)
//   y in [0,8)  : mt = 15-y,      piece 0, chunks [0, mt+1)     -> out
//   y in [8,16) : mt = 15-(y-8),  piece 1, chunks [mt+1, 2mt+2) -> g_po
//   y in [16,24): mt = 23-y,      full range [0, 2mt+2)         -> out
// ---------------------------------------------------------------------------
__global__ void __launch_bounds__(NTHREADS, 1)
pv_kernel(float* __restrict__ out)
{
    extern __shared__ char dsm[];
    const uint32_t Abase = (uint32_t)__cvta_generic_to_shared(dsm);
    const uint32_t Vbase = Abase + NSTG * ATILEB;

    const int b  = blockIdx.z;
    const int y  = blockIdx.y;
    int mt, c0, c1, piece;
    if (y < 8)        { mt = 15 - y;       piece = 0; c0 = 0;      c1 = mt + 1; }
    else if (y < 16)  { mt = 15 - (y - 8); piece = 1; c0 = mt + 1; c1 = 2 * (mt + 1); }
    else              { mt = 23 - y;       piece = 0; c0 = 0;      c1 = 2 * (mt + 1); }
    const int e0 = blockIdx.x * 256;

    const __half* P = g_ph + (size_t)b * SEQ * SEQ;
    const __half* V = g_qkvh[2] + (size_t)b * SEQ * EMB;

    const int m0 = mt * 128;
    const int tid = threadIdx.x;
    const int warp = tid >> 5, lane = tid & 31;
    const int wm = warp & 1, wn = warp >> 1;
    const int g = lane >> 2, tig = lane & 3;

    const int lr = tid >> 1;
    const int lc = (tid & 1) * 4;
    const __half* agp = P + (size_t)(m0 + lr) * SEQ;
    const uint32_t lxor = (uint32_t)(lr & 7);
    const int vr = tid >> 2;
    const int vcb = (tid & 3) * 8;
    const uint32_t vxor = (uint32_t)(vr & 7);

    const uint32_t a_row = (uint32_t)(wm * 64 + (lane & 15));
    const uint32_t a_chi = (uint32_t)(lane >> 4);
    const uint32_t a_xor = (uint32_t)(lane & 7);
    const uint32_t v_row = (uint32_t)(lane & 15);
    const uint32_t v_chi = (uint32_t)(lane >> 4);

    float acc[4][8][4];
#pragma unroll
    for (int i = 0; i < 4; i++)
#pragma unroll
        for (int j = 0; j < 8; j++)
#pragma unroll
            for (int k = 0; k < 4; k++) acc[i][j][k] = 0.f;

    auto pre = [&](int c, int s) {
        const __half* ap = agp + c * KC;
        const __half* vp = V + (size_t)(c * KC + vr) * EMB + e0;
        const uint32_t as = Abase + s * ATILEB + lr * 128;
        const uint32_t vs = Vbase + s * VTILEB + vr * 512;
#pragma unroll
        for (int j = 0; j < 4; j++) {
            const uint32_t c16 = lc + j;
            cp16(as + ((c16 ^ lxor) * 16), ap + c16 * 8);
        }
#pragma unroll
        for (int j = 0; j < 8; j++) {
            const uint32_t c16 = (uint32_t)(vcb + j);
            cp16(vs + (((c16 & 7u) ^ vxor) | (c16 & ~7u)) * 16, vp + c16 * 8);
        }
        cp_commit();
    };

    const int T = c1 - c0;
    pre(c0, 0);
    if (1 < T) pre(c0 + 1, 1);
    if (2 < T) pre(c0 + 2, 2);

    for (int t = 0; t < T; ++t) {
        if (t + 2 < T) cp_wait<2>(); else if (t + 1 < T) cp_wait<1>(); else cp_wait<0>();
        __syncthreads();
        if (t + 3 < T) pre(c0 + t + 3, (t + 3) & 3);

        const int s = t & 3;
        const uint32_t Ab = Abase + s * ATILEB;
        const uint32_t Vb = Vbase + s * VTILEB;
#pragma unroll
        for (int kk = 0; kk < 4; ++kk) {
            const uint32_t asw = ((kk * 2 + a_chi) ^ a_xor) * 16;
            uint32_t a[4][4];
#pragma unroll
            for (int mi = 0; mi < 4; ++mi)
                ldsm4(a[mi], Ab + (a_row + mi * 16) * 128 + asw);
            const uint32_t vrow = kk * 16 + v_row;
            const uint32_t vrx = vrow & 7;
            uint32_t b2[4][4];
#pragma unroll
            for (int p = 0; p < 4; ++p) {
                const uint32_t c16 = (uint32_t)(wn * 8 + p * 2) + v_chi;
                ldsm4t(b2[p], Vb + vrow * 512 + ((((c16 & 7u) ^ vrx) | (c16 & ~7u)) * 16));
            }
#pragma unroll
            for (int mi = 0; mi < 4; ++mi)
#pragma unroll
                for (int ni = 0; ni < 8; ++ni)
                    mma16(acc[mi][ni], a[mi], &b2[ni >> 1][(ni & 1) * 2]);
        }
    }

    float* obase = (piece == 1)
        ? g_po + (size_t)(b * 8 + (mt - 8)) * 128 * EMB
        : out + ((size_t)b * SEQ + m0) * EMB;

#pragma unroll
    for (int mi = 0; mi < 4; ++mi) {
        const int rloc = wm * 64 + mi * 16 + g;
#pragma unroll
        for (int ni = 0; ni < 8; ++ni) {
            const int col = e0 + wn * 64 + ni * 8 + 2 * tig;
            float2 r0 = {acc[mi][ni][0], acc[mi][ni][1]};
            float2 r1 = {acc[mi][ni][2], acc[mi][ni][3]};
            *(float2*)(obase + (size_t)rloc * EMB + col)       = r0;
            *(float2*)(obase + (size_t)(rloc + 8) * EMB + col) = r1;
        }
    }
}

// ---------------------------------------------------------------------------
// Kernel 5: fold split-K partials into out (rows of tiles mt>=8).
// ---------------------------------------------------------------------------
__global__ void __launch_bounds__(NTHREADS)
add_kernel(float* __restrict__ out)
{
    const int N4 = BATCH * 8 * 128 * EMB / 4;   // 1,048,576 float4s
    int i = blockIdx.x * NTHREADS + threadIdx.x;
    if (i >= N4) return;
    float4 p = ((const float4*)g_po)[i];
    const int c4 = i & (EMB / 4 - 1);
    const int rowflat = i >> 8;
    const int r = rowflat & 127;
    const int bm = rowflat >> 7;
    const int b = bm >> 3, mtl = bm & 7;
    const size_t o = ((size_t)(b * SEQ + (mtl + 8) * 128 + r) * EMB) / 4 + c4;
    float4 d = ((float4*)out)[o];
    d.x += p.x; d.y += p.y; d.z += p.z; d.w += p.w;
    ((float4*)out)[o] = d;
}

// ---------------------------------------------------------------------------
extern "C" void kernel_launch(void* const* d_in, const int* in_sizes, int n_in,
                              void* d_out, int out_size)
{
    const float* xs = (const float*)d_in[0];
    const float* wq = (const float*)d_in[1];
    const float* bq = (const float*)d_in[2];
    const float* wk = (const float*)d_in[3];
    const float* bk = (const float*)d_in[4];
    const float* wv = (const float*)d_in[5];
    const float* bv = (const float*)d_in[6];
    float* out = (float*)d_out;

    const int GEMM_SMEM = NSTG * (ATILEB + BTILEB);    // 196608 B
    cudaFuncSetAttribute(qkv_kernel,    cudaFuncAttributeMaxDynamicSharedMemorySize, GEMM_SMEM);
    cudaFuncSetAttribute(scores_kernel, cudaFuncAttributeMaxDynamicSharedMemorySize, GEMM_SMEM);
    cudaFuncSetAttribute(pv_kernel,     cudaFuncAttributeMaxDynamicSharedMemorySize, GEMM_SMEM);

    const int total4 = XN4 + 3 * WN4;
    cvt_kernel<<<(total4 + NTHREADS - 1) / NTHREADS, NTHREADS>>>(
        (const float4*)xs, (const float4*)wq, (const float4*)wk, (const float4*)wv);

    dim3 gqkv(EMB / 256, (BATCH * SEQ) / 128, 3);        // (4, 64, 3)
    qkv_kernel<<<gqkv, NTHREADS, GEMM_SMEM>>>(bq, bk, bv);

    dim3 gsc(SEQ / 256, SEQ / 128, BATCH);               // (8, 16, 4)
    scores_kernel<<<gsc, NTHREADS, GEMM_SMEM>>>();

    softmax_kernel<<<BATCH * SEQ, NTHREADS>>>();         // 8192 blocks

    dim3 gpv(EMB / 256, 24, BATCH);                      // (4, 24, 4)
    pv_kernel<<<gpv, NTHREADS, GEMM_SMEM>>>(out);

    const int addN4 = BATCH * 8 * 128 * EMB / 4;
    add_kernel<<<(addN4 + NTHREADS - 1) / NTHREADS, NTHREADS>>>(out);
}

// round 15
// speedup vs baseline: 1.0110x; 1.0110x over previous
#include <cuda_runtime.h>
#include <cuda_fp16.h>
#include <cstdint>

// Problem constants
#define BATCH 4
#define SEQ   2048
#define EMB   1024
#define HDIM  1024
#define NTHREADS 256

// GEMM tiling (R8-validated): CTA 128(M) x 256(N), warp tile 64x64, KC=64, 4 stages
#define KC      64
#define NSTG    4
#define ATILEB  (128 * 128)           // 16384 B
#define BTILEB  (256 * 128)           // 32768 B
#define VTILEB  (64 * 512)            // 32768 B : 64 k-rows x 512 B (256 e-cols)

// Scratch (static device allocations)
__device__ __half g_xh[(size_t)BATCH * SEQ * HDIM];      // fp16 x
__device__ __half g_wh[3][(size_t)EMB * HDIM];           // fp16 weights
__device__ __half g_qkvh[3][(size_t)BATCH * SEQ * EMB];  // fp16 Q,K,V
__device__ float  g_p[(size_t)BATCH * SEQ * SEQ];        // fp32 scores
__device__ __half g_ph[(size_t)BATCH * SEQ * SEQ];       // fp16 probs
__device__ float  g_po[(size_t)BATCH * 8 * 128 * EMB];   // pv split-K partials (mt>=8)

// ---------------------------------------------------------------------------
// PTX helpers
// ---------------------------------------------------------------------------
__device__ __forceinline__ void cp16(uint32_t dst, const void* src) {
    asm volatile("cp.async.ca.shared.global [%0], [%1], 16;" :: "r"(dst), "l"(src));
}
__device__ __forceinline__ void cp_commit() { asm volatile("cp.async.commit_group;"); }
template <int N>
__device__ __forceinline__ void cp_wait() { asm volatile("cp.async.wait_group %0;" :: "n"(N)); }

__device__ __forceinline__ void ldsm4(uint32_t* r, uint32_t addr) {
    asm volatile("ldmatrix.sync.aligned.m8n8.x4.shared.b16 {%0,%1,%2,%3}, [%4];"
                 : "=r"(r[0]), "=r"(r[1]), "=r"(r[2]), "=r"(r[3]) : "r"(addr));
}
__device__ __forceinline__ void ldsm4t(uint32_t* r, uint32_t addr) {
    asm volatile("ldmatrix.sync.aligned.m8n8.x4.trans.shared.b16 {%0,%1,%2,%3}, [%4];"
                 : "=r"(r[0]), "=r"(r[1]), "=r"(r[2]), "=r"(r[3]) : "r"(addr));
}
__device__ __forceinline__ void mma16(float* c, const uint32_t* a, const uint32_t* b) {
    asm volatile(
        "mma.sync.aligned.m16n8k16.row.col.f32.f16.f16.f32 "
        "{%0,%1,%2,%3}, {%4,%5,%6,%7}, {%8,%9}, {%0,%1,%2,%3};"
        : "+f"(c[0]), "+f"(c[1]), "+f"(c[2]), "+f"(c[3])
        : "r"(a[0]), "r"(a[1]), "r"(a[2]), "r"(a[3]), "r"(b[0]), "r"(b[1]));
}

// ---------------------------------------------------------------------------
// Kernel 0: single fp32 -> fp16 conversion pass for x + 3 weights.
// ---------------------------------------------------------------------------
#define XN4 ((BATCH * SEQ * HDIM) / 4)
#define WN4 ((EMB * HDIM) / 4)

__global__ void __launch_bounds__(NTHREADS)
cvt_kernel(const float4* __restrict__ xs, const float4* __restrict__ wq,
           const float4* __restrict__ wk, const float4* __restrict__ wv)
{
    int i = blockIdx.x * NTHREADS + threadIdx.x;
    const float4* src;
    __half* dst;
    int off;
    if (i < XN4)                { src = xs; dst = g_xh;    off = i; }
    else if (i < XN4 + WN4)     { src = wq; dst = g_wh[0]; off = i - XN4; }
    else if (i < XN4 + 2 * WN4) { src = wk; dst = g_wh[1]; off = i - XN4 - WN4; }
    else if (i < XN4 + 3 * WN4) { src = wv; dst = g_wh[2]; off = i - XN4 - 2 * WN4; }
    else return;
    float4 v = src[off];
    __half2 h0 = __floats2half2_rn(v.x, v.y);
    __half2 h1 = __floats2half2_rn(v.z, v.w);
    uint2 u;
    u.x = *reinterpret_cast<uint32_t*>(&h0);
    u.y = *reinterpret_cast<uint32_t*>(&h1);
    ((uint2*)dst)[off] = u;
}

// ---------------------------------------------------------------------------
// Kernel 1: QKV projection, NT fp16 GEMM + bias. grid (4, 64, 3).
// ---------------------------------------------------------------------------
__global__ void __launch_bounds__(NTHREADS, 1)
qkv_kernel(const float* __restrict__ bi0,
           const float* __restrict__ bi1,
           const float* __restrict__ bi2)
{
    extern __shared__ char dsm[];
    const uint32_t Abase = (uint32_t)__cvta_generic_to_shared(dsm);
    const uint32_t Bbase = Abase + NSTG * ATILEB;

    const int which = blockIdx.z;
    const __half* Ag = g_xh;
    const __half* Bg = g_wh[which];
    const float* bias = (which == 0) ? bi0 : (which == 1) ? bi1 : bi2;
    __half* out = g_qkvh[which];

    const int m0 = blockIdx.y * 128, n0 = blockIdx.x * 256;
    const int tid = threadIdx.x;
    const int warp = tid >> 5, lane = tid & 31;
    const int wm = warp & 1, wn = warp >> 1;
    const int g = lane >> 2, tig = lane & 3;

    const int lr = tid >> 1;
    const int lc = (tid & 1) * 4;
    const __half* agp = Ag + (size_t)(m0 + lr) * HDIM;
    const __half* bgp0 = Bg + (size_t)(n0 + lr) * HDIM;
    const __half* bgp1 = Bg + (size_t)(n0 + lr + 128) * HDIM;
    const uint32_t lxor = (uint32_t)(lr & 7);

    const uint32_t a_row = (uint32_t)(wm * 64 + (lane & 15));
    const uint32_t a_chi = (uint32_t)(lane >> 4);
    const uint32_t a_xor = (uint32_t)(lane & 7);
    const uint32_t b_row = (uint32_t)(wn * 64 + (lane & 7) + ((lane >> 4) & 1) * 8);
    const uint32_t b_chi = (uint32_t)((lane >> 3) & 1);

    float acc[4][8][4];
#pragma unroll
    for (int i = 0; i < 4; i++)
#pragma unroll
        for (int j = 0; j < 8; j++)
#pragma unroll
            for (int k = 0; k < 4; k++) acc[i][j][k] = 0.f;

    auto pre = [&](int c, int s) {
        const __half* ap = agp + c * KC;
        const __half* bp0 = bgp0 + c * KC;
        const __half* bp1 = bgp1 + c * KC;
        const uint32_t as = Abase + s * ATILEB + lr * 128;
        const uint32_t bs0 = Bbase + s * BTILEB + lr * 128;
        const uint32_t bs1 = bs0 + 128 * 128;
#pragma unroll
        for (int j = 0; j < 4; j++) {
            const uint32_t c16 = lc + j;
            const uint32_t sw = (c16 ^ lxor) * 16;
            cp16(as + sw,  ap + c16 * 8);
            cp16(bs0 + sw, bp0 + c16 * 8);
            cp16(bs1 + sw, bp1 + c16 * 8);
        }
        cp_commit();
    };

    const int T = HDIM / KC;   // 16
    pre(0, 0); pre(1, 1); pre(2, 2);

    for (int t = 0; t < T; ++t) {
        if (t + 2 < T) cp_wait<2>(); else if (t + 1 < T) cp_wait<1>(); else cp_wait<0>();
        __syncthreads();
        if (t + 3 < T) pre(t + 3, (t + 3) & 3);

        const int s = t & 3;
        const uint32_t Ab = Abase + s * ATILEB;
        const uint32_t Bb = Bbase + s * BTILEB;
#pragma unroll
        for (int kk = 0; kk < 4; ++kk) {
            const uint32_t asw = ((kk * 2 + a_chi) ^ a_xor) * 16;
            const uint32_t bsw = ((kk * 2 + b_chi) ^ a_xor) * 16;
            uint32_t a[4][4];
#pragma unroll
            for (int mi = 0; mi < 4; ++mi)
                ldsm4(a[mi], Ab + (a_row + mi * 16) * 128 + asw);
            uint32_t b[4][4];
#pragma unroll
            for (int p = 0; p < 4; ++p)
                ldsm4(b[p], Bb + (b_row + p * 16) * 128 + bsw);
#pragma unroll
            for (int mi = 0; mi < 4; ++mi)
#pragma unroll
                for (int ni = 0; ni < 8; ++ni)
                    mma16(acc[mi][ni], a[mi], &b[ni >> 1][(ni & 1) * 2]);
        }
    }

#pragma unroll
    for (int mi = 0; mi < 4; ++mi) {
        const int row = m0 + wm * 64 + mi * 16 + g;
#pragma unroll
        for (int ni = 0; ni < 8; ++ni) {
            const int col = n0 + wn * 64 + ni * 8 + 2 * tig;
            const float b0v = bias[col], b1v = bias[col + 1];
            __half2 h0 = __floats2half2_rn(acc[mi][ni][0] + b0v, acc[mi][ni][1] + b1v);
            __half2 h1 = __floats2half2_rn(acc[mi][ni][2] + b0v, acc[mi][ni][3] + b1v);
            *(__half2*)(out + (size_t)row * EMB + col)       = h0;
            *(__half2*)(out + (size_t)(row + 8) * EMB + col) = h1;
        }
    }
}

// ---------------------------------------------------------------------------
// Kernel 2: scores, NT fp16 GEMM, causal tiles only (2*nt <= qt), fp32 out.
// grid (8, 16, 4). CTA tile 128 x 256.
// ---------------------------------------------------------------------------
__global__ void __launch_bounds__(NTHREADS, 1)
scores_kernel()
{
    const int qt = blockIdx.y, nt = blockIdx.x;
    if (2 * nt > qt) return;
    const int b = blockIdx.z;

    extern __shared__ char dsm[];
    const uint32_t Abase = (uint32_t)__cvta_generic_to_shared(dsm);
    const uint32_t Bbase = Abase + NSTG * ATILEB;

    const __half* Q  = g_qkvh[0] + (size_t)b * SEQ * EMB;
    const __half* Km = g_qkvh[1] + (size_t)b * SEQ * EMB;
    float* P = g_p + (size_t)b * SEQ * SEQ;

    const int m0 = qt * 128, n0 = nt * 256;
    const int tid = threadIdx.x;
    const int warp = tid >> 5, lane = tid & 31;
    const int wm = warp & 1, wn = warp >> 1;
    const int g = lane >> 2, tig = lane & 3;

    const int lr = tid >> 1;
    const int lc = (tid & 1) * 4;
    const __half* agp = Q  + (size_t)(m0 + lr) * EMB;
    const __half* bgp0 = Km + (size_t)(n0 + lr) * EMB;
    const __half* bgp1 = Km + (size_t)(n0 + lr + 128) * EMB;
    const uint32_t lxor = (uint32_t)(lr & 7);

    const uint32_t a_row = (uint32_t)(wm * 64 + (lane & 15));
    const uint32_t a_chi = (uint32_t)(lane >> 4);
    const uint32_t a_xor = (uint32_t)(lane & 7);
    const uint32_t b_row = (uint32_t)(wn * 64 + (lane & 7) + ((lane >> 4) & 1) * 8);
    const uint32_t b_chi = (uint32_t)((lane >> 3) & 1);

    float acc[4][8][4];
#pragma unroll
    for (int i = 0; i < 4; i++)
#pragma unroll
        for (int j = 0; j < 8; j++)
#pragma unroll
            for (int k = 0; k < 4; k++) acc[i][j][k] = 0.f;

    auto pre = [&](int c, int s) {
        const __half* ap = agp + c * KC;
        const __half* bp0 = bgp0 + c * KC;
        const __half* bp1 = bgp1 + c * KC;
        const uint32_t as = Abase + s * ATILEB + lr * 128;
        const uint32_t bs0 = Bbase + s * BTILEB + lr * 128;
        const uint32_t bs1 = bs0 + 128 * 128;
#pragma unroll
        for (int j = 0; j < 4; j++) {
            const uint32_t c16 = lc + j;
            const uint32_t sw = (c16 ^ lxor) * 16;
            cp16(as + sw,  ap + c16 * 8);
            cp16(bs0 + sw, bp0 + c16 * 8);
            cp16(bs1 + sw, bp1 + c16 * 8);
        }
        cp_commit();
    };

    const int T = EMB / KC;   // 16
    pre(0, 0); pre(1, 1); pre(2, 2);

    for (int t = 0; t < T; ++t) {
        if (t + 2 < T) cp_wait<2>(); else if (t + 1 < T) cp_wait<1>(); else cp_wait<0>();
        __syncthreads();
        if (t + 3 < T) pre(t + 3, (t + 3) & 3);

        const int s = t & 3;
        const uint32_t Ab = Abase + s * ATILEB;
        const uint32_t Bb = Bbase + s * BTILEB;
#pragma unroll
        for (int kk = 0; kk < 4; ++kk) {
            const uint32_t asw = ((kk * 2 + a_chi) ^ a_xor) * 16;
            const uint32_t bsw = ((kk * 2 + b_chi) ^ a_xor) * 16;
            uint32_t a[4][4];
#pragma unroll
            for (int mi = 0; mi < 4; ++mi)
                ldsm4(a[mi], Ab + (a_row + mi * 16) * 128 + asw);
            uint32_t b[4][4];
#pragma unroll
            for (int p = 0; p < 4; ++p)
                ldsm4(b[p], Bb + (b_row + p * 16) * 128 + bsw);
#pragma unroll
            for (int mi = 0; mi < 4; ++mi)
#pragma unroll
                for (int ni = 0; ni < 8; ++ni)
                    mma16(acc[mi][ni], a[mi], &b[ni >> 1][(ni & 1) * 2]);
        }
    }

    const float scale = 0.03125f;  // 1/sqrt(1024)
#pragma unroll
    for (int mi = 0; mi < 4; ++mi) {
        const int row = m0 + wm * 64 + mi * 16 + g;
#pragma unroll
        for (int ni = 0; ni < 8; ++ni) {
            const int col = n0 + wn * 64 + ni * 8 + 2 * tig;
            float2 r0 = {acc[mi][ni][0] * scale, acc[mi][ni][1] * scale};
            float2 r1 = {acc[mi][ni][2] * scale, acc[mi][ni][3] * scale};
            *(float2*)(P + (size_t)row * SEQ + col)       = r0;
            *(float2*)(P + (size_t)(row + 8) * SEQ + col) = r1;
        }
    }
}

// ---------------------------------------------------------------------------
// Kernel 3: row softmax over [0..q]; fp16 probs out; vectorized passes.
// ---------------------------------------------------------------------------
__global__ void __launch_bounds__(NTHREADS)
softmax_kernel()
{
    __shared__ float buf[SEQ];
    __shared__ float red[8];

    const int q = blockIdx.x & (SEQ - 1);
    const int b = blockIdx.x >> 11;
    const float* row = g_p + ((size_t)b * SEQ + q) * SEQ;
    __half* orow = g_ph + ((size_t)b * SEQ + q) * SEQ;
    const int n = q + 1;
    const int zend = ((q >> 7) + 1) << 7;
    const int tid = threadIdx.x;
    const int lane = tid & 31;
    const int wid = tid >> 5;

    const float4* row4 = (const float4*)row;
    float4* buf4 = (float4*)buf;
    const int n4 = n >> 2;

    float lmax = -1e30f;
    for (int i = tid; i < n4; i += NTHREADS) {
        float4 v = row4[i];
        buf4[i] = v;
        lmax = fmaxf(lmax, fmaxf(fmaxf(v.x, v.y), fmaxf(v.z, v.w)));
    }
    for (int i = (n4 << 2) + tid; i < n; i += NTHREADS) {
        float v = row[i];
        buf[i] = v;
        lmax = fmaxf(lmax, v);
    }
#pragma unroll
    for (int off = 16; off; off >>= 1)
        lmax = fmaxf(lmax, __shfl_xor_sync(0xffffffffu, lmax, off));
    if (lane == 0) red[wid] = lmax;
    __syncthreads();
    float gmax = red[0];
#pragma unroll
    for (int w = 1; w < 8; w++) gmax = fmaxf(gmax, red[w]);
    __syncthreads();

    float lsum = 0.f;
    for (int i = tid; i < n4; i += NTHREADS) {
        float4 v = buf4[i];
        v.x = __expf(v.x - gmax); v.y = __expf(v.y - gmax);
        v.z = __expf(v.z - gmax); v.w = __expf(v.w - gmax);
        buf4[i] = v;
        lsum += (v.x + v.y) + (v.z + v.w);
    }
    for (int i = (n4 << 2) + tid; i < n; i += NTHREADS) {
        float e = __expf(buf[i] - gmax);
        buf[i] = e;
        lsum += e;
    }
#pragma unroll
    for (int off = 16; off; off >>= 1)
        lsum += __shfl_xor_sync(0xffffffffu, lsum, off);
    if (lane == 0) red[wid] = lsum;
    __syncthreads();
    float gsum = red[0];
#pragma unroll
    for (int w = 1; w < 8; w++) gsum += red[w];

    const float inv = 1.f / gsum;
    const int n2 = n >> 1;
    __half2* orow2 = (__half2*)orow;
    const float2* buf2 = (const float2*)buf;
    for (int i = tid; i < n2; i += NTHREADS) {
        float2 v = buf2[i];
        orow2[i] = __floats2half2_rn(v.x * inv, v.y * inv);
    }
    for (int i = (n2 << 1) + tid; i < n; i += NTHREADS)
        orow[i] = __float2half_rn(buf[i] * inv);
    const __half hz = __float2half_rn(0.f);
    for (int i = n + tid; i < zend; i += NTHREADS) orow[i] = hz;
}

// ---------------------------------------------------------------------------
// Kernel 4: O = P @ V, NN fp16 GEMM (V via ldmatrix.trans).
// Split-K(2) for mt >= 8: grid (4, 24, 4), heavy chains first.
//   y in [0,8)  : mt = 15-y,      piece 0, chunks [0, mt+1)     -> out
//   y in [8,16) : mt = 15-(y-8),  piece 1, chunks [mt+1, 2mt+2) -> g_po
//   y in [16,24): mt = 23-y,      full range [0, 2mt+2)         -> out
// ---------------------------------------------------------------------------
__global__ void __launch_bounds__(NTHREADS, 1)
pv_kernel(float* __restrict__ out)
{
    extern __shared__ char dsm[];
    const uint32_t Abase = (uint32_t)__cvta_generic_to_shared(dsm);
    const uint32_t Vbase = Abase + NSTG * ATILEB;

    const int b  = blockIdx.z;
    const int y  = blockIdx.y;
    int mt, c0, c1, piece;
    if (y < 8)        { mt = 15 - y;       piece = 0; c0 = 0;      c1 = mt + 1; }
    else if (y < 16)  { mt = 15 - (y - 8); piece = 1; c0 = mt + 1; c1 = 2 * (mt + 1); }
    else              { mt = 23 - y;       piece = 0; c0 = 0;      c1 = 2 * (mt + 1); }
    const int e0 = blockIdx.x * 256;

    const __half* P = g_ph + (size_t)b * SEQ * SEQ;
    const __half* V = g_qkvh[2] + (size_t)b * SEQ * EMB;

    const int m0 = mt * 128;
    const int tid = threadIdx.x;
    const int warp = tid >> 5, lane = tid & 31;
    const int wm = warp & 1, wn = warp >> 1;
    const int g = lane >> 2, tig = lane & 3;

    const int lr = tid >> 1;
    const int lc = (tid & 1) * 4;
    const __half* agp = P + (size_t)(m0 + lr) * SEQ;
    const uint32_t lxor = (uint32_t)(lr & 7);
    const int vr = tid >> 2;
    const int vcb = (tid & 3) * 8;
    const uint32_t vxor = (uint32_t)(vr & 7);

    const uint32_t a_row = (uint32_t)(wm * 64 + (lane & 15));
    const uint32_t a_chi = (uint32_t)(lane >> 4);
    const uint32_t a_xor = (uint32_t)(lane & 7);
    const uint32_t v_row = (uint32_t)(lane & 15);
    const uint32_t v_chi = (uint32_t)(lane >> 4);

    float acc[4][8][4];
#pragma unroll
    for (int i = 0; i < 4; i++)
#pragma unroll
        for (int j = 0; j < 8; j++)
#pragma unroll
            for (int k = 0; k < 4; k++) acc[i][j][k] = 0.f;

    auto pre = [&](int c, int s) {
        const __half* ap = agp + c * KC;
        const __half* vp = V + (size_t)(c * KC + vr) * EMB + e0;
        const uint32_t as = Abase + s * ATILEB + lr * 128;
        const uint32_t vs = Vbase + s * VTILEB + vr * 512;
#pragma unroll
        for (int j = 0; j < 4; j++) {
            const uint32_t c16 = lc + j;
            cp16(as + ((c16 ^ lxor) * 16), ap + c16 * 8);
        }
#pragma unroll
        for (int j = 0; j < 8; j++) {
            const uint32_t c16 = (uint32_t)(vcb + j);
            cp16(vs + (((c16 & 7u) ^ vxor) | (c16 & ~7u)) * 16, vp + c16 * 8);
        }
        cp_commit();
    };

    const int T = c1 - c0;
    pre(c0, 0);
    if (1 < T) pre(c0 + 1, 1);
    if (2 < T) pre(c0 + 2, 2);

    for (int t = 0; t < T; ++t) {
        if (t + 2 < T) cp_wait<2>(); else if (t + 1 < T) cp_wait<1>(); else cp_wait<0>();
        __syncthreads();
        if (t + 3 < T) pre(c0 + t + 3, (t + 3) & 3);

        const int s = t & 3;
        const uint32_t Ab = Abase + s * ATILEB;
        const uint32_t Vb = Vbase + s * VTILEB;
#pragma unroll
        for (int kk = 0; kk < 4; ++kk) {
            const uint32_t asw = ((kk * 2 + a_chi) ^ a_xor) * 16;
            uint32_t a[4][4];
#pragma unroll
            for (int mi = 0; mi < 4; ++mi)
                ldsm4(a[mi], Ab + (a_row + mi * 16) * 128 + asw);
            const uint32_t vrow = kk * 16 + v_row;
            const uint32_t vrx = vrow & 7;
            uint32_t b2[4][4];
#pragma unroll
            for (int p = 0; p < 4; ++p) {
                const uint32_t c16 = (uint32_t)(wn * 8 + p * 2) + v_chi;
                ldsm4t(b2[p], Vb + vrow * 512 + ((((c16 & 7u) ^ vrx) | (c16 & ~7u)) * 16));
            }
#pragma unroll
            for (int mi = 0; mi < 4; ++mi)
#pragma unroll
                for (int ni = 0; ni < 8; ++ni)
                    mma16(acc[mi][ni], a[mi], &b2[ni >> 1][(ni & 1) * 2]);
        }
    }

    float* obase = (piece == 1)
        ? g_po + (size_t)(b * 8 + (mt - 8)) * 128 * EMB
        : out + ((size_t)b * SEQ + m0) * EMB;

#pragma unroll
    for (int mi = 0; mi < 4; ++mi) {
        const int rloc = wm * 64 + mi * 16 + g;
#pragma unroll
        for (int ni = 0; ni < 8; ++ni) {
            const int col = e0 + wn * 64 + ni * 8 + 2 * tig;
            float2 r0 = {acc[mi][ni][0], acc[mi][ni][1]};
            float2 r1 = {acc[mi][ni][2], acc[mi][ni][3]};
            *(float2*)(obase + (size_t)rloc * EMB + col)       = r0;
            *(float2*)(obase + (size_t)(rloc + 8) * EMB + col) = r1;
        }
    }
}

// ---------------------------------------------------------------------------
// Kernel 5: fold split-K partials into out (rows of tiles mt>=8).
// ---------------------------------------------------------------------------
__global__ void __launch_bounds__(NTHREADS)
add_kernel(float* __restrict__ out)
{
    const int N4 = BATCH * 8 * 128 * EMB / 4;   // 1,048,576 float4s
    int i = blockIdx.x * NTHREADS + threadIdx.x;
    if (i >= N4) return;
    float4 p = ((const float4*)g_po)[i];
    const int c4 = i & (EMB / 4 - 1);
    const int rowflat = i >> 8;
    const int r = rowflat & 127;
    const int bm = rowflat >> 7;
    const int b = bm >> 3, mtl = bm & 7;
    const size_t o = ((size_t)(b * SEQ + (mtl + 8) * 128 + r) * EMB) / 4 + c4;
    float4 d = ((float4*)out)[o];
    d.x += p.x; d.y += p.y; d.z += p.z; d.w += p.w;
    ((float4*)out)[o] = d;
}

// ---------------------------------------------------------------------------
extern "C" void kernel_launch(void* const* d_in, const int* in_sizes, int n_in,
                              void* d_out, int out_size)
{
    const float* xs = (const float*)d_in[0];
    const float* wq = (const float*)d_in[1];
    const float* bq = (const float*)d_in[2];
    const float* wk = (const float*)d_in[3];
    const float* bk = (const float*)d_in[4];
    const float* wv = (const float*)d_in[5];
    const float* bv = (const float*)d_in[6];
    float* out = (float*)d_out;

    const int GEMM_SMEM = NSTG * (ATILEB + BTILEB);    // 196608 B
    cudaFuncSetAttribute(qkv_kernel,    cudaFuncAttributeMaxDynamicSharedMemorySize, GEMM_SMEM);
    cudaFuncSetAttribute(scores_kernel, cudaFuncAttributeMaxDynamicSharedMemorySize, GEMM_SMEM);
    cudaFuncSetAttribute(pv_kernel,     cudaFuncAttributeMaxDynamicSharedMemorySize, GEMM_SMEM);

    const int total4 = XN4 + 3 * WN4;
    cvt_kernel<<<(total4 + NTHREADS - 1) / NTHREADS, NTHREADS>>>(
        (const float4*)xs, (const float4*)wq, (const float4*)wk, (const float4*)wv);

    dim3 gqkv(EMB / 256, (BATCH * SEQ) / 128, 3);        // (4, 64, 3)
    qkv_kernel<<<gqkv, NTHREADS, GEMM_SMEM>>>(bq, bk, bv);

    dim3 gsc(SEQ / 256, SEQ / 128, BATCH);               // (8, 16, 4)
    scores_kernel<<<gsc, NTHREADS, GEMM_SMEM>>>();

    softmax_kernel<<<BATCH * SEQ, NTHREADS>>>();         // 8192 blocks

    dim3 gpv(EMB / 256, 24, BATCH);                      // (4, 24, 4)
    pv_kernel<<<gpv, NTHREADS, GEMM_SMEM>>>(out);

    const int addN4 = BATCH * 8 * 128 * EMB / 4;
    add_kernel<<<(addN4 + NTHREADS - 1) / NTHREADS, NTHREADS>>>(out);
}

// round 16
// speedup vs baseline: 1.0382x; 1.0268x over previous
#include <cuda_runtime.h>
#include <cuda_fp16.h>
#include <cstdint>

// Problem constants
#define BATCH 4
#define SEQ   2048
#define EMB   1024
#define HDIM  1024
#define NTHREADS 256

// GEMM tiling (R8-validated): CTA 128(M) x 256(N), warp tile 64x64, KC=64, 4 stages
#define KC      64
#define NSTG    4
#define ATILEB  (128 * 128)           // 16384 B
#define BTILEB  (256 * 128)           // 32768 B
#define VTILEB  (64 * 512)            // 32768 B : 64 k-rows x 512 B (256 e-cols)

// Scratch (static device allocations)
__device__ __half g_xh[(size_t)BATCH * SEQ * HDIM];      // fp16 x
__device__ __half g_wh[3][(size_t)EMB * HDIM];           // fp16 weights
__device__ __half g_qkvh[3][(size_t)BATCH * SEQ * EMB];  // fp16 Q,K,V
__device__ float  g_p[(size_t)BATCH * SEQ * SEQ];        // fp32 scores
__device__ __half g_ph[(size_t)BATCH * SEQ * SEQ];       // fp16 probs
__device__ float  g_po[(size_t)BATCH * 8 * 128 * EMB];   // pv split-K partials (mt>=8)

// ---------------------------------------------------------------------------
// PTX helpers
// ---------------------------------------------------------------------------
__device__ __forceinline__ void cp16(uint32_t dst, const void* src) {
    asm volatile("cp.async.ca.shared.global [%0], [%1], 16;" :: "r"(dst), "l"(src));
}
__device__ __forceinline__ void cp_commit() { asm volatile("cp.async.commit_group;"); }
template <int N>
__device__ __forceinline__ void cp_wait() { asm volatile("cp.async.wait_group %0;" :: "n"(N)); }

__device__ __forceinline__ void ldsm4(uint32_t* r, uint32_t addr) {
    asm volatile("ldmatrix.sync.aligned.m8n8.x4.shared.b16 {%0,%1,%2,%3}, [%4];"
                 : "=r"(r[0]), "=r"(r[1]), "=r"(r[2]), "=r"(r[3]) : "r"(addr));
}
__device__ __forceinline__ void ldsm4t(uint32_t* r, uint32_t addr) {
    asm volatile("ldmatrix.sync.aligned.m8n8.x4.trans.shared.b16 {%0,%1,%2,%3}, [%4];"
                 : "=r"(r[0]), "=r"(r[1]), "=r"(r[2]), "=r"(r[3]) : "r"(addr));
}
__device__ __forceinline__ void mma16(float* c, const uint32_t* a, const uint32_t* b) {
    asm volatile(
        "mma.sync.aligned.m16n8k16.row.col.f32.f16.f16.f32 "
        "{%0,%1,%2,%3}, {%4,%5,%6,%7}, {%8,%9}, {%0,%1,%2,%3};"
        : "+f"(c[0]), "+f"(c[1]), "+f"(c[2]), "+f"(c[3])
        : "r"(a[0]), "r"(a[1]), "r"(a[2]), "r"(a[3]), "r"(b[0]), "r"(b[1]));
}

// ---------------------------------------------------------------------------
// Kernel 0: single fp32 -> fp16 conversion pass for x + 3 weights.
// ---------------------------------------------------------------------------
#define XN4 ((BATCH * SEQ * HDIM) / 4)
#define WN4 ((EMB * HDIM) / 4)

__global__ void __launch_bounds__(NTHREADS)
cvt_kernel(const float4* __restrict__ xs, const float4* __restrict__ wq,
           const float4* __restrict__ wk, const float4* __restrict__ wv)
{
    int i = blockIdx.x * NTHREADS + threadIdx.x;
    const float4* src;
    __half* dst;
    int off;
    if (i < XN4)                { src = xs; dst = g_xh;    off = i; }
    else if (i < XN4 + WN4)     { src = wq; dst = g_wh[0]; off = i - XN4; }
    else if (i < XN4 + 2 * WN4) { src = wk; dst = g_wh[1]; off = i - XN4 - WN4; }
    else if (i < XN4 + 3 * WN4) { src = wv; dst = g_wh[2]; off = i - XN4 - 2 * WN4; }
    else return;
    float4 v = src[off];
    __half2 h0 = __floats2half2_rn(v.x, v.y);
    __half2 h1 = __floats2half2_rn(v.z, v.w);
    uint2 u;
    u.x = *reinterpret_cast<uint32_t*>(&h0);
    u.y = *reinterpret_cast<uint32_t*>(&h1);
    ((uint2*)dst)[off] = u;
}

// ---------------------------------------------------------------------------
// Kernel 1: QKV projection, NT fp16 GEMM + bias. grid (4, 64, 3).
// kk-loop software-pipelined: fragment loads for kk+1 issued before MMAs of kk.
// MMA order/operands identical to R11 -> bitwise-identical results.
// ---------------------------------------------------------------------------
__global__ void __launch_bounds__(NTHREADS, 1)
qkv_kernel(const float* __restrict__ bi0,
           const float* __restrict__ bi1,
           const float* __restrict__ bi2)
{
    extern __shared__ char dsm[];
    const uint32_t Abase = (uint32_t)__cvta_generic_to_shared(dsm);
    const uint32_t Bbase = Abase + NSTG * ATILEB;

    const int which = blockIdx.z;
    const __half* Ag = g_xh;
    const __half* Bg = g_wh[which];
    const float* bias = (which == 0) ? bi0 : (which == 1) ? bi1 : bi2;
    __half* out = g_qkvh[which];

    const int m0 = blockIdx.y * 128, n0 = blockIdx.x * 256;
    const int tid = threadIdx.x;
    const int warp = tid >> 5, lane = tid & 31;
    const int wm = warp & 1, wn = warp >> 1;
    const int g = lane >> 2, tig = lane & 3;

    const int lr = tid >> 1;
    const int lc = (tid & 1) * 4;
    const __half* agp = Ag + (size_t)(m0 + lr) * HDIM;
    const __half* bgp0 = Bg + (size_t)(n0 + lr) * HDIM;
    const __half* bgp1 = Bg + (size_t)(n0 + lr + 128) * HDIM;
    const uint32_t lxor = (uint32_t)(lr & 7);

    const uint32_t a_row = (uint32_t)(wm * 64 + (lane & 15));
    const uint32_t a_chi = (uint32_t)(lane >> 4);
    const uint32_t a_xor = (uint32_t)(lane & 7);
    const uint32_t b_row = (uint32_t)(wn * 64 + (lane & 7) + ((lane >> 4) & 1) * 8);
    const uint32_t b_chi = (uint32_t)((lane >> 3) & 1);

    float acc[4][8][4];
#pragma unroll
    for (int i = 0; i < 4; i++)
#pragma unroll
        for (int j = 0; j < 8; j++)
#pragma unroll
            for (int k = 0; k < 4; k++) acc[i][j][k] = 0.f;

    auto pre = [&](int c, int s) {
        const __half* ap = agp + c * KC;
        const __half* bp0 = bgp0 + c * KC;
        const __half* bp1 = bgp1 + c * KC;
        const uint32_t as = Abase + s * ATILEB + lr * 128;
        const uint32_t bs0 = Bbase + s * BTILEB + lr * 128;
        const uint32_t bs1 = bs0 + 128 * 128;
#pragma unroll
        for (int j = 0; j < 4; j++) {
            const uint32_t c16 = lc + j;
            const uint32_t sw = (c16 ^ lxor) * 16;
            cp16(as + sw,  ap + c16 * 8);
            cp16(bs0 + sw, bp0 + c16 * 8);
            cp16(bs1 + sw, bp1 + c16 * 8);
        }
        cp_commit();
    };

    const int T = HDIM / KC;   // 16
    pre(0, 0); pre(1, 1); pre(2, 2);

    for (int t = 0; t < T; ++t) {
        if (t + 2 < T) cp_wait<2>(); else if (t + 1 < T) cp_wait<1>(); else cp_wait<0>();
        __syncthreads();
        if (t + 3 < T) pre(t + 3, (t + 3) & 3);

        const int s = t & 3;
        const uint32_t Ab = Abase + s * ATILEB;
        const uint32_t Bb = Bbase + s * BTILEB;

        uint32_t aA[4][4], bA[4][4], aB[4][4], bB[4][4];
        auto ldA = [&](uint32_t (&r)[4][4], int kk) {
#pragma unroll
            for (int mi = 0; mi < 4; ++mi)
                ldsm4(r[mi], Ab + (a_row + mi * 16) * 128 +
                             (((uint32_t)(kk * 2) + a_chi) ^ a_xor) * 16);
        };
        auto ldB = [&](uint32_t (&r)[4][4], int kk) {
#pragma unroll
            for (int p = 0; p < 4; ++p)
                ldsm4(r[p], Bb + (b_row + p * 16) * 128 +
                            (((uint32_t)(kk * 2) + b_chi) ^ a_xor) * 16);
        };
        auto domma = [&](uint32_t (&a)[4][4], uint32_t (&b)[4][4]) {
#pragma unroll
            for (int mi = 0; mi < 4; ++mi)
#pragma unroll
                for (int ni = 0; ni < 8; ++ni)
                    mma16(acc[mi][ni], a[mi], &b[ni >> 1][(ni & 1) * 2]);
        };

        ldA(aA, 0); ldB(bA, 0);
        ldA(aB, 1); ldB(bB, 1);
        domma(aA, bA);
        ldA(aA, 2); ldB(bA, 2);
        domma(aB, bB);
        ldA(aB, 3); ldB(bB, 3);
        domma(aA, bA);
        domma(aB, bB);
    }

#pragma unroll
    for (int mi = 0; mi < 4; ++mi) {
        const int row = m0 + wm * 64 + mi * 16 + g;
#pragma unroll
        for (int ni = 0; ni < 8; ++ni) {
            const int col = n0 + wn * 64 + ni * 8 + 2 * tig;
            const float b0v = bias[col], b1v = bias[col + 1];
            __half2 h0 = __floats2half2_rn(acc[mi][ni][0] + b0v, acc[mi][ni][1] + b1v);
            __half2 h1 = __floats2half2_rn(acc[mi][ni][2] + b0v, acc[mi][ni][3] + b1v);
            *(__half2*)(out + (size_t)row * EMB + col)       = h0;
            *(__half2*)(out + (size_t)(row + 8) * EMB + col) = h1;
        }
    }
}

// ---------------------------------------------------------------------------
// Kernel 2: scores, NT fp16 GEMM, causal tiles only (2*nt <= qt), fp32 out.
// grid (8, 16, 4). CTA tile 128 x 256. Same kk pipelining.
// ---------------------------------------------------------------------------
__global__ void __launch_bounds__(NTHREADS, 1)
scores_kernel()
{
    const int qt = blockIdx.y, nt = blockIdx.x;
    if (2 * nt > qt) return;
    const int b = blockIdx.z;

    extern __shared__ char dsm[];
    const uint32_t Abase = (uint32_t)__cvta_generic_to_shared(dsm);
    const uint32_t Bbase = Abase + NSTG * ATILEB;

    const __half* Q  = g_qkvh[0] + (size_t)b * SEQ * EMB;
    const __half* Km = g_qkvh[1] + (size_t)b * SEQ * EMB;
    float* P = g_p + (size_t)b * SEQ * SEQ;

    const int m0 = qt * 128, n0 = nt * 256;
    const int tid = threadIdx.x;
    const int warp = tid >> 5, lane = tid & 31;
    const int wm = warp & 1, wn = warp >> 1;
    const int g = lane >> 2, tig = lane & 3;

    const int lr = tid >> 1;
    const int lc = (tid & 1) * 4;
    const __half* agp = Q  + (size_t)(m0 + lr) * EMB;
    const __half* bgp0 = Km + (size_t)(n0 + lr) * EMB;
    const __half* bgp1 = Km + (size_t)(n0 + lr + 128) * EMB;
    const uint32_t lxor = (uint32_t)(lr & 7);

    const uint32_t a_row = (uint32_t)(wm * 64 + (lane & 15));
    const uint32_t a_chi = (uint32_t)(lane >> 4);
    const uint32_t a_xor = (uint32_t)(lane & 7);
    const uint32_t b_row = (uint32_t)(wn * 64 + (lane & 7) + ((lane >> 4) & 1) * 8);
    const uint32_t b_chi = (uint32_t)((lane >> 3) & 1);

    float acc[4][8][4];
#pragma unroll
    for (int i = 0; i < 4; i++)
#pragma unroll
        for (int j = 0; j < 8; j++)
#pragma unroll
            for (int k = 0; k < 4; k++) acc[i][j][k] = 0.f;

    auto pre = [&](int c, int s) {
        const __half* ap = agp + c * KC;
        const __half* bp0 = bgp0 + c * KC;
        const __half* bp1 = bgp1 + c * KC;
        const uint32_t as = Abase + s * ATILEB + lr * 128;
        const uint32_t bs0 = Bbase + s * BTILEB + lr * 128;
        const uint32_t bs1 = bs0 + 128 * 128;
#pragma unroll
        for (int j = 0; j < 4; j++) {
            const uint32_t c16 = lc + j;
            const uint32_t sw = (c16 ^ lxor) * 16;
            cp16(as + sw,  ap + c16 * 8);
            cp16(bs0 + sw, bp0 + c16 * 8);
            cp16(bs1 + sw, bp1 + c16 * 8);
        }
        cp_commit();
    };

    const int T = EMB / KC;   // 16
    pre(0, 0); pre(1, 1); pre(2, 2);

    for (int t = 0; t < T; ++t) {
        if (t + 2 < T) cp_wait<2>(); else if (t + 1 < T) cp_wait<1>(); else cp_wait<0>();
        __syncthreads();
        if (t + 3 < T) pre(t + 3, (t + 3) & 3);

        const int s = t & 3;
        const uint32_t Ab = Abase + s * ATILEB;
        const uint32_t Bb = Bbase + s * BTILEB;

        uint32_t aA[4][4], bA[4][4], aB[4][4], bB[4][4];
        auto ldA = [&](uint32_t (&r)[4][4], int kk) {
#pragma unroll
            for (int mi = 0; mi < 4; ++mi)
                ldsm4(r[mi], Ab + (a_row + mi * 16) * 128 +
                             (((uint32_t)(kk * 2) + a_chi) ^ a_xor) * 16);
        };
        auto ldB = [&](uint32_t (&r)[4][4], int kk) {
#pragma unroll
            for (int p = 0; p < 4; ++p)
                ldsm4(r[p], Bb + (b_row + p * 16) * 128 +
                            (((uint32_t)(kk * 2) + b_chi) ^ a_xor) * 16);
        };
        auto domma = [&](uint32_t (&a)[4][4], uint32_t (&b)[4][4]) {
#pragma unroll
            for (int mi = 0; mi < 4; ++mi)
#pragma unroll
                for (int ni = 0; ni < 8; ++ni)
                    mma16(acc[mi][ni], a[mi], &b[ni >> 1][(ni & 1) * 2]);
        };

        ldA(aA, 0); ldB(bA, 0);
        ldA(aB, 1); ldB(bB, 1);
        domma(aA, bA);
        ldA(aA, 2); ldB(bA, 2);
        domma(aB, bB);
        ldA(aB, 3); ldB(bB, 3);
        domma(aA, bA);
        domma(aB, bB);
    }

    const float scale = 0.03125f;  // 1/sqrt(1024)
#pragma unroll
    for (int mi = 0; mi < 4; ++mi) {
        const int row = m0 + wm * 64 + mi * 16 + g;
#pragma unroll
        for (int ni = 0; ni < 8; ++ni) {
            const int col = n0 + wn * 64 + ni * 8 + 2 * tig;
            float2 r0 = {acc[mi][ni][0] * scale, acc[mi][ni][1] * scale};
            float2 r1 = {acc[mi][ni][2] * scale, acc[mi][ni][3] * scale};
            *(float2*)(P + (size_t)row * SEQ + col)       = r0;
            *(float2*)(P + (size_t)(row + 8) * SEQ + col) = r1;
        }
    }
}

// ---------------------------------------------------------------------------
// Kernel 3: row softmax over [0..q]; fp16 probs out; vectorized passes.
// ---------------------------------------------------------------------------
__global__ void __launch_bounds__(NTHREADS)
softmax_kernel()
{
    __shared__ float buf[SEQ];
    __shared__ float red[8];

    const int q = blockIdx.x & (SEQ - 1);
    const int b = blockIdx.x >> 11;
    const float* row = g_p + ((size_t)b * SEQ + q) * SEQ;
    __half* orow = g_ph + ((size_t)b * SEQ + q) * SEQ;
    const int n = q + 1;
    const int zend = ((q >> 7) + 1) << 7;
    const int tid = threadIdx.x;
    const int lane = tid & 31;
    const int wid = tid >> 5;

    const float4* row4 = (const float4*)row;
    float4* buf4 = (float4*)buf;
    const int n4 = n >> 2;

    float lmax = -1e30f;
    for (int i = tid; i < n4; i += NTHREADS) {
        float4 v = row4[i];
        buf4[i] = v;
        lmax = fmaxf(lmax, fmaxf(fmaxf(v.x, v.y), fmaxf(v.z, v.w)));
    }
    for (int i = (n4 << 2) + tid; i < n; i += NTHREADS) {
        float v = row[i];
        buf[i] = v;
        lmax = fmaxf(lmax, v);
    }
#pragma unroll
    for (int off = 16; off; off >>= 1)
        lmax = fmaxf(lmax, __shfl_xor_sync(0xffffffffu, lmax, off));
    if (lane == 0) red[wid] = lmax;
    __syncthreads();
    float gmax = red[0];
#pragma unroll
    for (int w = 1; w < 8; w++) gmax = fmaxf(gmax, red[w]);
    __syncthreads();

    float lsum = 0.f;
    for (int i = tid; i < n4; i += NTHREADS) {
        float4 v = buf4[i];
        v.x = __expf(v.x - gmax); v.y = __expf(v.y - gmax);
        v.z = __expf(v.z - gmax); v.w = __expf(v.w - gmax);
        buf4[i] = v;
        lsum += (v.x + v.y) + (v.z + v.w);
    }
    for (int i = (n4 << 2) + tid; i < n; i += NTHREADS) {
        float e = __expf(buf[i] - gmax);
        buf[i] = e;
        lsum += e;
    }
#pragma unroll
    for (int off = 16; off; off >>= 1)
        lsum += __shfl_xor_sync(0xffffffffu, lsum, off);
    if (lane == 0) red[wid] = lsum;
    __syncthreads();
    float gsum = red[0];
#pragma unroll
    for (int w = 1; w < 8; w++) gsum += red[w];

    const float inv = 1.f / gsum;
    const int n2 = n >> 1;
    __half2* orow2 = (__half2*)orow;
    const float2* buf2 = (const float2*)buf;
    for (int i = tid; i < n2; i += NTHREADS) {
        float2 v = buf2[i];
        orow2[i] = __floats2half2_rn(v.x * inv, v.y * inv);
    }
    for (int i = (n2 << 1) + tid; i < n; i += NTHREADS)
        orow[i] = __float2half_rn(buf[i] * inv);
    const __half hz = __float2half_rn(0.f);
    for (int i = n + tid; i < zend; i += NTHREADS) orow[i] = hz;
}

// ---------------------------------------------------------------------------
// Kernel 4: O = P @ V, NN fp16 GEMM (V via ldmatrix.trans).
// Split-K(2) for mt >= 8: grid (4, 24, 4), heavy chains first.
// Same kk pipelining as qkv/scores.
// ---------------------------------------------------------------------------
__global__ void __launch_bounds__(NTHREADS, 1)
pv_kernel(float* __restrict__ out)
{
    extern __shared__ char dsm[];
    const uint32_t Abase = (uint32_t)__cvta_generic_to_shared(dsm);
    const uint32_t Vbase = Abase + NSTG * ATILEB;

    const int b  = blockIdx.z;
    const int y  = blockIdx.y;
    int mt, c0, c1, piece;
    if (y < 8)        { mt = 15 - y;       piece = 0; c0 = 0;      c1 = mt + 1; }
    else if (y < 16)  { mt = 15 - (y - 8); piece = 1; c0 = mt + 1; c1 = 2 * (mt + 1); }
    else              { mt = 23 - y;       piece = 0; c0 = 0;      c1 = 2 * (mt + 1); }
    const int e0 = blockIdx.x * 256;

    const __half* P = g_ph + (size_t)b * SEQ * SEQ;
    const __half* V = g_qkvh[2] + (size_t)b * SEQ * EMB;

    const int m0 = mt * 128;
    const int tid = threadIdx.x;
    const int warp = tid >> 5, lane = tid & 31;
    const int wm = warp & 1, wn = warp >> 1;
    const int g = lane >> 2, tig = lane & 3;

    const int lr = tid >> 1;
    const int lc = (tid & 1) * 4;
    const __half* agp = P + (size_t)(m0 + lr) * SEQ;
    const uint32_t lxor = (uint32_t)(lr & 7);
    const int vr = tid >> 2;
    const int vcb = (tid & 3) * 8;
    const uint32_t vxor = (uint32_t)(vr & 7);

    const uint32_t a_row = (uint32_t)(wm * 64 + (lane & 15));
    const uint32_t a_chi = (uint32_t)(lane >> 4);
    const uint32_t a_xor = (uint32_t)(lane & 7);
    const uint32_t v_row = (uint32_t)(lane & 15);
    const uint32_t v_chi = (uint32_t)(lane >> 4);

    float acc[4][8][4];
#pragma unroll
    for (int i = 0; i < 4; i++)
#pragma unroll
        for (int j = 0; j < 8; j++)
#pragma unroll
            for (int k = 0; k < 4; k++) acc[i][j][k] = 0.f;

    auto pre = [&](int c, int s) {
        const __half* ap = agp + c * KC;
        const __half* vp = V + (size_t)(c * KC + vr) * EMB + e0;
        const uint32_t as = Abase + s * ATILEB + lr * 128;
        const uint32_t vs = Vbase + s * VTILEB + vr * 512;
#pragma unroll
        for (int j = 0; j < 4; j++) {
            const uint32_t c16 = lc + j;
            cp16(as + ((c16 ^ lxor) * 16), ap + c16 * 8);
        }
#pragma unroll
        for (int j = 0; j < 8; j++) {
            const uint32_t c16 = (uint32_t)(vcb + j);
            cp16(vs + (((c16 & 7u) ^ vxor) | (c16 & ~7u)) * 16, vp + c16 * 8);
        }
        cp_commit();
    };

    const int T = c1 - c0;
    pre(c0, 0);
    if (1 < T) pre(c0 + 1, 1);
    if (2 < T) pre(c0 + 2, 2);

    for (int t = 0; t < T; ++t) {
        if (t + 2 < T) cp_wait<2>(); else if (t + 1 < T) cp_wait<1>(); else cp_wait<0>();
        __syncthreads();
        if (t + 3 < T) pre(c0 + t + 3, (t + 3) & 3);

        const int s = t & 3;
        const uint32_t Ab = Abase + s * ATILEB;
        const uint32_t Vb = Vbase + s * VTILEB;

        uint32_t aA[4][4], bA[4][4], aB[4][4], bB[4][4];
        auto ldA = [&](uint32_t (&r)[4][4], int kk) {
#pragma unroll
            for (int mi = 0; mi < 4; ++mi)
                ldsm4(r[mi], Ab + (a_row + mi * 16) * 128 +
                             (((uint32_t)(kk * 2) + a_chi) ^ a_xor) * 16);
        };
        auto ldV = [&](uint32_t (&r)[4][4], int kk) {
            const uint32_t vrow = (uint32_t)(kk * 16) + v_row;
            const uint32_t vrx = vrow & 7;
#pragma unroll
            for (int p = 0; p < 4; ++p) {
                const uint32_t c16 = (uint32_t)(wn * 8 + p * 2) + v_chi;
                ldsm4t(r[p], Vb + vrow * 512 + ((((c16 & 7u) ^ vrx) | (c16 & ~7u)) * 16));
            }
        };
        auto domma = [&](uint32_t (&a)[4][4], uint32_t (&b)[4][4]) {
#pragma unroll
            for (int mi = 0; mi < 4; ++mi)
#pragma unroll
                for (int ni = 0; ni < 8; ++ni)
                    mma16(acc[mi][ni], a[mi], &b[ni >> 1][(ni & 1) * 2]);
        };

        ldA(aA, 0); ldV(bA, 0);
        ldA(aB, 1); ldV(bB, 1);
        domma(aA, bA);
        ldA(aA, 2); ldV(bA, 2);
        domma(aB, bB);
        ldA(aB, 3); ldV(bB, 3);
        domma(aA, bA);
        domma(aB, bB);
    }

    float* obase = (piece == 1)
        ? g_po + (size_t)(b * 8 + (mt - 8)) * 128 * EMB
        : out + ((size_t)b * SEQ + m0) * EMB;

#pragma unroll
    for (int mi = 0; mi < 4; ++mi) {
        const int rloc = wm * 64 + mi * 16 + g;
#pragma unroll
        for (int ni = 0; ni < 8; ++ni) {
            const int col = e0 + wn * 64 + ni * 8 + 2 * tig;
            float2 r0 = {acc[mi][ni][0], acc[mi][ni][1]};
            float2 r1 = {acc[mi][ni][2], acc[mi][ni][3]};
            *(float2*)(obase + (size_t)rloc * EMB + col)       = r0;
            *(float2*)(obase + (size_t)(rloc + 8) * EMB + col) = r1;
        }
    }
}

// ---------------------------------------------------------------------------
// Kernel 5: fold split-K partials into out (rows of tiles mt>=8).
// ---------------------------------------------------------------------------
__global__ void __launch_bounds__(NTHREADS)
add_kernel(float* __restrict__ out)
{
    const int N4 = BATCH * 8 * 128 * EMB / 4;   // 1,048,576 float4s
    int i = blockIdx.x * NTHREADS + threadIdx.x;
    if (i >= N4) return;
    float4 p = ((const float4*)g_po)[i];
    const int c4 = i & (EMB / 4 - 1);
    const int rowflat = i >> 8;
    const int r = rowflat & 127;
    const int bm = rowflat >> 7;
    const int b = bm >> 3, mtl = bm & 7;
    const size_t o = ((size_t)(b * SEQ + (mtl + 8) * 128 + r) * EMB) / 4 + c4;
    float4 d = ((float4*)out)[o];
    d.x += p.x; d.y += p.y; d.z += p.z; d.w += p.w;
    ((float4*)out)[o] = d;
}

// ---------------------------------------------------------------------------
extern "C" void kernel_launch(void* const* d_in, const int* in_sizes, int n_in,
                              void* d_out, int out_size)
{
    const float* xs = (const float*)d_in[0];
    const float* wq = (const float*)d_in[1];
    const float* bq = (const float*)d_in[2];
    const float* wk = (const float*)d_in[3];
    const float* bk = (const float*)d_in[4];
    const float* wv = (const float*)d_in[5];
    const float* bv = (const float*)d_in[6];
    float* out = (float*)d_out;

    const int GEMM_SMEM = NSTG * (ATILEB + BTILEB);    // 196608 B
    cudaFuncSetAttribute(qkv_kernel,    cudaFuncAttributeMaxDynamicSharedMemorySize, GEMM_SMEM);
    cudaFuncSetAttribute(scores_kernel, cudaFuncAttributeMaxDynamicSharedMemorySize, GEMM_SMEM);
    cudaFuncSetAttribute(pv_kernel,     cudaFuncAttributeMaxDynamicSharedMemorySize, GEMM_SMEM);

    const int total4 = XN4 + 3 * WN4;
    cvt_kernel<<<(total4 + NTHREADS - 1) / NTHREADS, NTHREADS>>>(
        (const float4*)xs, (const float4*)wq, (const float4*)wk, (const float4*)wv);

    dim3 gqkv(EMB / 256, (BATCH * SEQ) / 128, 3);        // (4, 64, 3)
    qkv_kernel<<<gqkv, NTHREADS, GEMM_SMEM>>>(bq, bk, bv);

    dim3 gsc(SEQ / 256, SEQ / 128, BATCH);               // (8, 16, 4)
    scores_kernel<<<gsc, NTHREADS, GEMM_SMEM>>>();

    softmax_kernel<<<BATCH * SEQ, NTHREADS>>>();         // 8192 blocks

    dim3 gpv(EMB / 256, 24, BATCH);                      // (4, 24, 4)
    pv_kernel<<<gpv, NTHREADS, GEMM_SMEM>>>(out);

    const int addN4 = BATCH * 8 * 128 * EMB / 4;
    add_kernel<<<(addN4 + NTHREADS - 1) / NTHREADS, NTHREADS>>>(out);
}